// round 1
// baseline (speedup 1.0000x reference)
#include <cuda_runtime.h>
#include <cuda_bf16.h>
#include <cstdint>

#define TLEN 512
#define HID  256
#define EMB  256
#define VOC  32000
#define NROW 2048   // 2 cells * 4H gate rows

// Scratch (static device globals — no runtime allocation)
__device__ float g_X[TLEN * NROW];               // 4 MB   precomputed x@W_ih^T + biases
__device__ float g_S[TLEN * 2 * HID];            // 1 MB   s_t = [hf, cf]
__device__ float g_logits[(size_t)TLEN * VOC];   // 64 MB  logits before log_softmax
__device__ float g_rowoff[TLEN];                 // per-row (max + log sum exp)

__device__ __forceinline__ uint32_t smem_u32(const void* p) {
    return (uint32_t)__cvta_generic_to_shared(p);
}

// ---------------------------------------------------------------------------
// K1: X[t][row] = emb[token_t] . w_ih[row] + b_ih[row] + b_hh[row]
//     rows 0..1023 forward cell, 1024..2047 backward cell
// grid (16 t-blocks of 32, 16 row-blocks of 128), 256 threads
// ---------------------------------------------------------------------------
__global__ __launch_bounds__(256) void k1_precompute(
    const float* __restrict__ emb_table, const int* __restrict__ target,
    const float* __restrict__ wihf, const float* __restrict__ bihf, const float* __restrict__ bhhf,
    const float* __restrict__ wihb, const float* __restrict__ bihb, const float* __restrict__ bhhb)
{
    __shared__ float se[32][EMB];   // 32 KB of embedded tokens for this t-block
    const int tblk = blockIdx.x * 32;
    const int rblk = blockIdx.y * 128;

    for (int i = threadIdx.x; i < 32 * EMB; i += 256) {
        int tt = i >> 8;          // / EMB
        int k  = i & 255;
        int t  = tblk + tt;
        int tok = (t == 0) ? 0 : target[t - 1];   // teacher forcing with SOS=0
        se[tt][k] = emb_table[(size_t)tok * EMB + k];
    }
    __syncthreads();

    const int row_l = threadIdx.x & 127;
    const int th    = threadIdx.x >> 7;   // which 16-t half
    const int row   = rblk + row_l;

    const float* w;
    float bias;
    if (row < 1024) { w = wihf + (size_t)row * EMB;               bias = bihf[row] + bhhf[row]; }
    else            { int r2 = row - 1024; w = wihb + (size_t)r2 * EMB; bias = bihb[r2] + bhhb[r2]; }

    float acc[16];
#pragma unroll
    for (int i = 0; i < 16; i++) acc[i] = 0.f;

    for (int k = 0; k < EMB; k += 4) {
        float4 wv = *(const float4*)(w + k);
#pragma unroll
        for (int i = 0; i < 16; i++) {
            float4 e = *(const float4*)&se[th * 16 + i][k];   // broadcast LDS
            acc[i] += wv.x * e.x + wv.y * e.y + wv.z * e.z + wv.w * e.w;
        }
    }
#pragma unroll
    for (int i = 0; i < 16; i++) {
        int t = tblk + th * 16 + i;
        g_X[t * NROW + row] = acc[i] + bias;
    }
}

// ---------------------------------------------------------------------------
// K2: the sequential bilstm recurrence.
// grid = 16 CTAs, cluster of 8 per cell (blocks 0-7 = forward, 8-15 = backward).
// Each CTA owns 32 units (128 gate rows). W_hh held in REGISTERS as packed
// f32x2 (64 x 64-bit regs per thread; 2 threads per gate row, K split 128/128).
// h broadcast across the cluster each step via DSMEM stores + cluster barrier.
// ---------------------------------------------------------------------------
__global__ void __cluster_dims__(8, 1, 1) __launch_bounds__(256, 1)
k2_lstm(const float* __restrict__ whhf, const float* __restrict__ whhb,
        float* __restrict__ out_seq)
{
    __shared__ float sh_h[2][256];   // double-buffered h (whole cell)
    __shared__ float sh_g[128];      // this CTA's 128 gate pre-activations

    uint32_t rank;
    asm("mov.u32 %0, %%cluster_ctarank;" : "=r"(rank));
    const int cell = blockIdx.x >> 3;
    const float* whh = cell ? whhb : whhf;

    const int tid   = threadIdx.x;
    const int row_l = tid >> 1;        // 0..127 local gate row
    const int khalf = tid & 1;         // which K half (128 each)
    const int gate  = row_l >> 5;      // 0..3 (i,f,g,o)
    const int ul    = row_l & 31;      // unit within CTA
    const int unit  = (int)rank * 32 + ul;
    const int grow  = gate * 256 + unit;      // row of w_hh [1024 x 256]

    // register-resident weights, packed as f32x2
    unsigned long long w[64];
    {
        const float2* wp = (const float2*)(whh + (size_t)grow * HID + khalf * 128);
#pragma unroll
        for (int j = 0; j < 64; j++) {
            float2 v = wp[j];
            asm("mov.b64 %0, {%1, %2};" : "=l"(w[j]) : "f"(v.x), "f"(v.y));
        }
    }

    sh_h[0][tid] = 0.f;     // h0 = 0 (256 threads cover 256 slots)
    float c_reg = 0.f;      // thread tid<32 owns c for unit rank*32+tid
    __syncthreads();

    const int xrow = cell * 1024 + grow;

    for (int t = 0; t < TLEN; t++) {
        const int p = t & 1;
        float xv = __ldg(&g_X[t * NROW + xrow]);   // prefetched early

        const unsigned long long* hp = (const unsigned long long*)&sh_h[p][khalf * 128];
        unsigned long long a0 = 0ULL, a1 = 0ULL, a2 = 0ULL, a3 = 0ULL;
#pragma unroll
        for (int j = 0; j < 64; j += 4) {
            asm("fma.rn.f32x2 %0, %1, %2, %0;" : "+l"(a0) : "l"(w[j + 0]), "l"(hp[j + 0]));
            asm("fma.rn.f32x2 %0, %1, %2, %0;" : "+l"(a1) : "l"(w[j + 1]), "l"(hp[j + 1]));
            asm("fma.rn.f32x2 %0, %1, %2, %0;" : "+l"(a2) : "l"(w[j + 2]), "l"(hp[j + 2]));
            asm("fma.rn.f32x2 %0, %1, %2, %0;" : "+l"(a3) : "l"(w[j + 3]), "l"(hp[j + 3]));
        }
        float lo0, hi0, lo1, hi1, lo2, hi2, lo3, hi3;
        asm("mov.b64 {%0, %1}, %2;" : "=f"(lo0), "=f"(hi0) : "l"(a0));
        asm("mov.b64 {%0, %1}, %2;" : "=f"(lo1), "=f"(hi1) : "l"(a1));
        asm("mov.b64 {%0, %1}, %2;" : "=f"(lo2), "=f"(hi2) : "l"(a2));
        asm("mov.b64 {%0, %1}, %2;" : "=f"(lo3), "=f"(hi3) : "l"(a3));
        float sum = ((lo0 + hi0) + (lo1 + hi1)) + ((lo2 + hi2) + (lo3 + hi3));
        sum += __shfl_xor_sync(0xffffffffu, sum, 1);   // combine the two K halves

        if (khalf == 0) sh_g[gate * 32 + ul] = sum + xv;
        __syncthreads();

        if (tid < 32) {
            float zi = sh_g[tid], zf = sh_g[32 + tid], zc = sh_g[64 + tid], zo = sh_g[96 + tid];
            float ig = 1.f / (1.f + expf(-zi));
            float fg = 1.f / (1.f + expf(-zf));
            float gc = tanhf(zc);
            float og = 1.f / (1.f + expf(-zo));
            c_reg = fg * c_reg + ig * gc;
            float hv = og * tanhf(c_reg);

            const int u = (int)rank * 32 + tid;
            if (cell == 0) {
                out_seq[t * 512 + u] = hv;              // outputs[:, :256] = hf
                g_S[t * 512 + u] = hv;                  // s[:, :256]   = hf
                g_S[t * 512 + 256 + u] = c_reg;         // s[:, 256:]   = cf
            } else {
                out_seq[t * 512 + 256 + u] = hv;        // outputs[:, 256:] = hb
            }

            // broadcast h_next to every CTA in the cluster (incl. self)
            uint32_t laddr = smem_u32(&sh_h[p ^ 1][u]);
#pragma unroll
            for (int d = 0; d < 8; d++) {
                uint32_t raddr;
                asm("mapa.shared::cluster.u32 %0, %1, %2;" : "=r"(raddr) : "r"(laddr), "r"(d));
                asm volatile("st.shared::cluster.f32 [%0], %1;" :: "r"(raddr), "f"(hv) : "memory");
            }
        }
        // release-arrive orders the DSMEM stores; wait acquires them
        asm volatile("barrier.cluster.arrive.aligned;" ::: "memory");
        asm volatile("barrier.cluster.wait.aligned;"   ::: "memory");
    }
}

// ---------------------------------------------------------------------------
// K3a: logits[512, 32000] = S[512,512] @ test_w^T + test_b   (bf16 mma, fp32 acc)
// CTA tile 128x128, BK=32, 256 threads (2x4 warps, warp tile 64x32), dbl-buffered.
// ---------------------------------------------------------------------------
#define BM 128
#define BN 128
#define BK 32
#define KPAD 40

#define STORE_STAGE(buf)                                                            \
    do {                                                                            \
        _Pragma("unroll")                                                           \
        for (int q = 0; q < 4; q++) {                                               \
            int c = lhalf * 16 + q * 4;                                             \
            *(__nv_bfloat162*)&sA[buf][lrow][c]     = __floats2bfloat162_rn(ra[q].x, ra[q].y); \
            *(__nv_bfloat162*)&sA[buf][lrow][c + 2] = __floats2bfloat162_rn(ra[q].z, ra[q].w); \
            *(__nv_bfloat162*)&sB[buf][lrow][c]     = __floats2bfloat162_rn(rb[q].x, rb[q].y); \
            *(__nv_bfloat162*)&sB[buf][lrow][c + 2] = __floats2bfloat162_rn(rb[q].z, rb[q].w); \
        }                                                                           \
    } while (0)

__global__ __launch_bounds__(256) void k3a_gemm(
    const float* __restrict__ testw, const float* __restrict__ testb)
{
    __shared__ __nv_bfloat16 sA[2][BM][KPAD];
    __shared__ __nv_bfloat16 sB[2][BN][KPAD];

    const int tid   = threadIdx.x;
    const int Mb    = blockIdx.y * BM;
    const int Nb    = blockIdx.x * BN;
    const int lrow  = tid >> 1;
    const int lhalf = tid & 1;
    const int warp  = tid >> 5, lane = tid & 31;
    const int wm = warp >> 2, wn = warp & 3;
    const int gq = lane >> 2, tg = lane & 3;

    float acc[4][4][4];
#pragma unroll
    for (int a = 0; a < 4; a++)
#pragma unroll
        for (int b = 0; b < 4; b++)
#pragma unroll
            for (int c = 0; c < 4; c++) acc[a][b][c] = 0.f;

    const float* Aptr = g_S   + (size_t)(Mb + lrow) * 512 + lhalf * 16;
    const float* Bptr = testw + (size_t)(Nb + lrow) * 512 + lhalf * 16;

    float4 ra[4], rb[4];
#pragma unroll
    for (int q = 0; q < 4; q++) {
        ra[q] = *(const float4*)(Aptr + q * 4);
        rb[q] = *(const float4*)(Bptr + q * 4);
    }
    STORE_STAGE(0);
    __syncthreads();

    for (int kt = 0; kt < 16; kt++) {
        const int cur = kt & 1;
        if (kt < 15) {
#pragma unroll
            for (int q = 0; q < 4; q++) {
                ra[q] = *(const float4*)(Aptr + (kt + 1) * 32 + q * 4);
                rb[q] = *(const float4*)(Bptr + (kt + 1) * 32 + q * 4);
            }
        }
#pragma unroll
        for (int kk = 0; kk < 32; kk += 16) {
            uint32_t af[4][4], bf[4][2];
#pragma unroll
            for (int mt = 0; mt < 4; mt++) {
                int r0 = wm * 64 + mt * 16 + gq;
                af[mt][0] = *(const uint32_t*)&sA[cur][r0][kk + tg * 2];
                af[mt][1] = *(const uint32_t*)&sA[cur][r0 + 8][kk + tg * 2];
                af[mt][2] = *(const uint32_t*)&sA[cur][r0][kk + tg * 2 + 8];
                af[mt][3] = *(const uint32_t*)&sA[cur][r0 + 8][kk + tg * 2 + 8];
            }
#pragma unroll
            for (int nt = 0; nt < 4; nt++) {
                int c0 = wn * 32 + nt * 8 + gq;
                bf[nt][0] = *(const uint32_t*)&sB[cur][c0][kk + tg * 2];
                bf[nt][1] = *(const uint32_t*)&sB[cur][c0][kk + tg * 2 + 8];
            }
#pragma unroll
            for (int mt = 0; mt < 4; mt++)
#pragma unroll
                for (int nt = 0; nt < 4; nt++) {
                    asm("mma.sync.aligned.m16n8k16.row.col.f32.bf16.bf16.f32 "
                        "{%0,%1,%2,%3}, {%4,%5,%6,%7}, {%8,%9}, {%0,%1,%2,%3};"
                        : "+f"(acc[mt][nt][0]), "+f"(acc[mt][nt][1]),
                          "+f"(acc[mt][nt][2]), "+f"(acc[mt][nt][3])
                        : "r"(af[mt][0]), "r"(af[mt][1]), "r"(af[mt][2]), "r"(af[mt][3]),
                          "r"(bf[nt][0]), "r"(bf[nt][1]));
                }
        }
        if (kt < 15) STORE_STAGE(cur ^ 1);
        __syncthreads();
    }

#pragma unroll
    for (int nt = 0; nt < 4; nt++) {
        int n = Nb + wn * 32 + nt * 8 + tg * 2;
        float2 tb = *(const float2*)(testb + n);
#pragma unroll
        for (int mt = 0; mt < 4; mt++) {
            int m0 = Mb + wm * 64 + mt * 16 + gq;
            float2 v0 = make_float2(acc[mt][nt][0] + tb.x, acc[mt][nt][1] + tb.y);
            float2 v1 = make_float2(acc[mt][nt][2] + tb.x, acc[mt][nt][3] + tb.y);
            *(float2*)&g_logits[(size_t)m0 * VOC + n] = v0;
            *(float2*)&g_logits[(size_t)(m0 + 8) * VOC + n] = v1;
        }
    }
}

// ---------------------------------------------------------------------------
// K3b: per-row max + log-sum-exp (logits live in L2 after K3a)
// ---------------------------------------------------------------------------
__global__ __launch_bounds__(256) void k3b_reduce()
{
    __shared__ float red[256];
    const int t = blockIdx.x;
    const float* row = g_logits + (size_t)t * VOC;

    float m = -1e30f;
    for (int i = threadIdx.x; i < VOC; i += 256) m = fmaxf(m, row[i]);
    red[threadIdx.x] = m;
    __syncthreads();
    for (int s = 128; s > 0; s >>= 1) {
        if (threadIdx.x < s) red[threadIdx.x] = fmaxf(red[threadIdx.x], red[threadIdx.x + s]);
        __syncthreads();
    }
    m = red[0];
    __syncthreads();

    float sum = 0.f;
    for (int i = threadIdx.x; i < VOC; i += 256) sum += __expf(row[i] - m);
    red[threadIdx.x] = sum;
    __syncthreads();
    for (int s = 128; s > 0; s >>= 1) {
        if (threadIdx.x < s) red[threadIdx.x] += red[threadIdx.x + s];
        __syncthreads();
    }
    if (threadIdx.x == 0) g_rowoff[t] = m + logf(red[0]);
}

// ---------------------------------------------------------------------------
// K3c: Pvocab = logits - (max + logZ)
// ---------------------------------------------------------------------------
__global__ __launch_bounds__(256) void k3c_finalize(float* __restrict__ out)
{
    size_t i = ((size_t)blockIdx.x * 256 + threadIdx.x) * 4;
    int t = (int)(i / VOC);           // VOC divisible by 4 -> same t for all 4
    float off = g_rowoff[t];
    float4 v = *(const float4*)&g_logits[i];
    v.x -= off; v.y -= off; v.z -= off; v.w -= off;
    *(float4*)&out[i] = v;
}

// ---------------------------------------------------------------------------
extern "C" void kernel_launch(void* const* d_in, const int* in_sizes, int n_in,
                              void* d_out, int out_size)
{
    const float* emb   = (const float*)d_in[1];
    const float* wihf  = (const float*)d_in[2];
    const float* whhf  = (const float*)d_in[3];
    const float* bihf  = (const float*)d_in[4];
    const float* bhhf  = (const float*)d_in[5];
    const float* wihb  = (const float*)d_in[6];
    const float* whhb  = (const float*)d_in[7];
    const float* bihb  = (const float*)d_in[8];
    const float* bhhb  = (const float*)d_in[9];
    const float* testw = (const float*)d_in[20];
    const float* testb = (const float*)d_in[21];
    const int*   tgt   = (const int*)d_in[22];

    float* out_pv  = (float*)d_out;                       // Pvocab [512, 1, 32000]
    float* out_seq = out_pv + (size_t)TLEN * VOC;         // outputs [512, 512]

    k1_precompute<<<dim3(16, 16), 256>>>(emb, tgt, wihf, bihf, bhhf, wihb, bihb, bhhb);
    k2_lstm<<<16, 256>>>(whhf, whhb, out_seq);
    k3a_gemm<<<dim3(250, 4), 256>>>(testw, testb);
    k3b_reduce<<<TLEN, 256>>>();
    k3c_finalize<<<(TLEN * VOC / 4) / 256, 256>>>(out_pv);
}